// round 9
// baseline (speedup 1.0000x reference)
#include <cuda_runtime.h>
#include <cstdint>

// AdaptiveSparseVoxels: expand N parents -> 8N children.
// Output (float32): [8N x 32] row-major features, then 8N morton-as-float.
// Row layout: px py pz size dens c0..c26 (32 floats = 128B)
//
// R9: double-buffered TMA store pipeline. Evidence (R5/R6/R8): all STG
// variants pin at ~5 TB/s with every unit at ~60% => per-SM store-datapath
// rate limit. Escape: build tiles in SMEM (STS, 128B/cyc/SM) and drain via
// cp.async.bulk shared::cta->global (async proxy, bypasses STG path).
// Unlike R7 (serial tile+full drain per CTA), each CTA processes GPB groups
// with 2 tile buffers: group i+1's compute overlaps group i's TMA drain;
// buffer reuse guarded by wait_group.read<=1.
//
// Group = 16 parents: tile 16KB + mort 512B. smem ~= 2*16.5KB + 2KB ~= 35KB
// -> ~6 CTAs/SM resident.

#define TPB 256
#define PPG 16             // parents per group
#define WPB 8              // warps per block
#define WP  (PPG / WPB)    // parents per warp in compute phase (=2)

__device__ __forceinline__ unsigned part1by2(unsigned n) {
    n &= 1023u;
    n = (n ^ (n << 16)) & 0xFF0000FFu;
    n = (n ^ (n << 8))  & 0x0300F00Fu;
    n = (n ^ (n << 4))  & 0x030C30C3u;
    n = (n ^ (n << 2))  & 0x09249249u;
    return n;
}

__device__ __forceinline__ unsigned coord_of(float p, float fres, int resm1) {
    // reference: ((p + 1) / 2 * res).astype(int32) then clip(0, res-1)
    float norm = __fmul_rn(__fmul_rn(__fadd_rn(p, 1.0f), 0.5f), fres);
    int c = (int)norm;                 // trunc toward zero == astype(int32)
    c = c < 0 ? 0 : (c > resm1 ? resm1 : c);
    return (unsigned)c;
}

__device__ __forceinline__ unsigned smem_u32(const void* p) {
    return (unsigned)__cvta_generic_to_shared(p);
}

__global__ void __launch_bounds__(TPB)
asv_expand_kernel(
    const float* __restrict__ positions,   // [N,3]
    const float* __restrict__ sizes,       // [N]
    const float* __restrict__ densities,   // [N]
    const float* __restrict__ colors,      // [N,27]
    const int*   __restrict__ level_p,     // [1]
    float*       __restrict__ out,         // [8N*32] + [8N] morton-as-float
    unsigned N, unsigned nrows,            // nrows = 8N
    unsigned ngroups, unsigned gpb)        // groups of PPG parents; per block
{
    __shared__ __align__(16) float tile[2][PPG * 256];  // 2 x 16KB
    __shared__ __align__(16) float mort[2][PPG * 8];    // 2 x 512B
    __shared__ __align__(16) float rec [PPG * 32];      // 2KB, per-iteration

    const unsigned tid  = threadIdx.x;
    const unsigned lane = tid & 31u;
    const unsigned wid  = tid >> 5;

    const int   res   = 64 << __ldg(level_p);
    const float fres  = (float)res;
    const int   resm1 = res - 1;

    for (unsigned it = 0; it < gpb; it++) {
        const unsigned g = blockIdx.x * gpb + it;
        if (g >= ngroups) break;
        const unsigned pbase = g * PPG;
        const unsigned nP    = (N - pbase < PPG) ? (N - pbase) : PPG;
        const unsigned buf   = it & 1u;

        // ---- ensure tile[buf] (used by TMA of iteration it-2) is drained ----
        if (it >= 2u && tid == 0u)
            asm volatile("cp.async.bulk.wait_group.read 1;" ::: "memory");

        // ---- stage parent records in OUTPUT layout @ stride 32 ----
        // (rec reads from it-1's compute are all done: end-of-iter sync)
        for (unsigned i = tid; i < nP * 27u; i += TPB) {
            unsigned p = i / 27u, c = i - p * 27u;
            rec[p * 32u + 5u + c] = colors[(pbase + p) * 27u + c];
        }
        if (tid < nP * 3u) {
            unsigned p = tid / 3u, c = tid - p * 3u;
            rec[p * 32u + c] = positions[(pbase + p) * 3u + c];
        }
        if (tid < nP) {
            rec[tid * 32u + 3u] = sizes[pbase + tid];
            rec[tid * 32u + 4u] = densities[pbase + tid];
        }
        __syncthreads();   // rec visible + tile[buf] drained (tid0 waited)

        // ---- compute feature tile (STS, conflict-free 512B warp-ops) ----
        {
            const unsigned j  = lane & 7u;   // float4 column of the row
            const unsigned rg = lane >> 3;   // row within 4-row group

            #pragma unroll
            for (unsigned w = 0; w < WP; w++) {
                const unsigned pl = wid * WP + w;
                if (pl >= nP) break;

                const float* r  = &rec[pl * 32u];
                const float4 v  = *reinterpret_cast<const float4*>(r + 4u * j);
                const float4 ps = *reinterpret_cast<const float4*>(r);

                const float s  = ps.w;
                const float qd = 0.25f * s;  // exact
                const float hs = 0.5f  * s;  // exact

                float* tb = &tile[buf][pl * 256u];

                #pragma unroll
                for (unsigned t = 0; t < 2; t++) {
                    const unsigned oct = 4u * t + rg;
                    float4 sv = v;
                    if (j == 0u) {
                        sv.x = __fadd_rn(ps.x, (oct & 1u) ? qd : -qd);
                        sv.y = __fadd_rn(ps.y, (oct & 2u) ? qd : -qd);
                        sv.z = __fadd_rn(ps.z, (oct & 4u) ? qd : -qd);
                        sv.w = hs;
                    }
                    *reinterpret_cast<float4*>(tb + oct * 32u + 4u * j) = sv;
                }
            }
        }

        // ---- morton tile (full-lane packed, tid < nP*8 <= 128) ----
        if (tid < nP * 8u) {
            const unsigned pl  = tid >> 3;
            const unsigned oct = tid & 7u;

            const float4 ps = *reinterpret_cast<const float4*>(&rec[pl * 32u]);
            const float qd = 0.25f * ps.w;
            float px = __fadd_rn(ps.x, (oct & 1u) ? qd : -qd);
            float py = __fadd_rn(ps.y, (oct & 2u) ? qd : -qd);
            float pz = __fadd_rn(ps.z, (oct & 4u) ? qd : -qd);

            unsigned code = (part1by2(coord_of(pz, fres, resm1)) << 2)
                          + (part1by2(coord_of(py, fres, resm1)) << 1)
                          +  part1by2(coord_of(px, fres, resm1));
            mort[buf][tid] = (float)(int)code;  // exact: code < 2^21 at lvl 1
        }

        __syncthreads();   // all STS for this tile complete

        // ---- issue async bulk copies (overlap with next iteration) ----
        if (tid == 0u) {
            asm volatile("fence.proxy.async.shared::cta;" ::: "memory");

            const float* gfeat = out + (size_t)pbase * 256u;
            const float* gmort = out + (size_t)nrows * 32u + (size_t)pbase * 8u;
            unsigned feat_bytes = nP * 1024u;   // multiple of 16
            unsigned mort_bytes = nP * 32u;     // multiple of 16

            asm volatile(
                "cp.async.bulk.global.shared::cta.bulk_group [%0], [%1], %2;"
                :: "l"(gfeat), "r"(smem_u32(&tile[buf][0])), "r"(feat_bytes)
                : "memory");
            asm volatile(
                "cp.async.bulk.global.shared::cta.bulk_group [%0], [%1], %2;"
                :: "l"(gmort), "r"(smem_u32(&mort[buf][0])), "r"(mort_bytes)
                : "memory");
            asm volatile("cp.async.bulk.commit_group;" ::: "memory");
        }
        __syncthreads();   // nobody overwrites rec until commit is placed
    }

    // ---- tail: keep CTA resident until TMA has read all its smem ----
    if (tid == 0u)
        asm volatile("cp.async.bulk.wait_group.read 0;" ::: "memory");
}

extern "C" void kernel_launch(void* const* d_in, const int* in_sizes, int n_in,
                              void* d_out, int out_size) {
    const float* positions = (const float*)d_in[0];
    const float* sizes     = (const float*)d_in[1];
    const float* densities = (const float*)d_in[2];
    const float* colors    = (const float*)d_in[3];
    const int*   level     = (const int*)d_in[4];

    unsigned N       = (unsigned)(in_sizes[0] / 3);
    unsigned nrows   = N * 8u;
    unsigned ngroups = (N + PPG - 1) / PPG;

    unsigned blocks = 2048;
    if (blocks > ngroups) blocks = ngroups;
    unsigned gpb = (ngroups + blocks - 1) / blocks;

    asv_expand_kernel<<<blocks, TPB>>>(
        positions, sizes, densities, colors, level,
        (float*)d_out, N, nrows, ngroups, gpb);
}

// round 10
// speedup vs baseline: 1.2957x; 1.2957x over previous
#include <cuda_runtime.h>
#include <cstdint>

// AdaptiveSparseVoxels: expand N parents -> 8N children.
// Output (float32): [8N x 32] row-major features, then 8N morton-as-float.
// Row layout: px py pz size dens c0..c26 (32 floats = 128B)
//
// R10: HYBRID dual-path store drain. Block = 32 parents.
//  - Warps 0-5 (STG path): parents 0-23, R6 mapping (j=lane&7 column float4,
//    rg=lane>>3; warp-op = 512B contiguous STG.128). Then packed morton for
//    their 192 children (threads 0-191, one per child).
//  - Warps 6-7 (TMA path): parents 24-31 -> build 8KB feature tile + 256B
//    morton tile in SMEM (same lane mapping, STS), named-barrier sync of the
//    64 threads, then ONE thread issues cp.async.bulk (shared::cta->global)
//    for both tiles and waits .read 0 at CTA end.
// Purpose: STG->L1 wavefront path and async-proxy path drain in parallel.

#define TPB 256
#define PPB 32             // parents per block
#define P_STG 24           // parents on STG path (warps 0-5, 4 per warp)
#define P_TMA 8            // parents on TMA path (warps 6-7, 4 per warp)

__device__ __forceinline__ unsigned part1by2(unsigned n) {
    n &= 1023u;
    n = (n ^ (n << 16)) & 0xFF0000FFu;
    n = (n ^ (n << 8))  & 0x0300F00Fu;
    n = (n ^ (n << 4))  & 0x030C30C3u;
    n = (n ^ (n << 2))  & 0x09249249u;
    return n;
}

__device__ __forceinline__ unsigned coord_of(float p, float fres, int resm1) {
    // reference: ((p + 1) / 2 * res).astype(int32) then clip(0, res-1)
    float norm = __fmul_rn(__fmul_rn(__fadd_rn(p, 1.0f), 0.5f), fres);
    int c = (int)norm;                 // trunc toward zero == astype(int32)
    c = c < 0 ? 0 : (c > resm1 ? resm1 : c);
    return (unsigned)c;
}

__device__ __forceinline__ unsigned smem_u32(const void* p) {
    return (unsigned)__cvta_generic_to_shared(p);
}

__global__ void __launch_bounds__(TPB)
asv_expand_kernel(
    const float* __restrict__ positions,   // [N,3]
    const float* __restrict__ sizes,       // [N]
    const float* __restrict__ densities,   // [N]
    const float* __restrict__ colors,      // [N,27]
    const int*   __restrict__ level_p,     // [1]
    float*       __restrict__ out,         // [8N*32] + [8N] morton-as-float
    unsigned N, unsigned nrows)            // nrows = 8N
{
    __shared__ __align__(16) float rec [PPB * 32];    // 4KB parent records
    __shared__ __align__(16) float tile[P_TMA * 256]; // 8KB TMA feature tile
    __shared__ __align__(16) float mtile[P_TMA * 8];  // 256B TMA morton tile

    const unsigned tid   = threadIdx.x;
    const unsigned pbase = blockIdx.x * PPB;
    const unsigned nP    = (N - pbase < PPB) ? (N - pbase) : PPB;

    // ---- Stage parent records in OUTPUT layout @ stride 32 floats ----
    for (unsigned i = tid; i < nP * 27u; i += TPB) {
        unsigned p = i / 27u, c = i - p * 27u;
        rec[p * 32u + 5u + c] = colors[(pbase + p) * 27u + c];
    }
    if (tid < nP * 3u) {
        unsigned p = tid / 3u, c = tid - p * 3u;
        rec[p * 32u + c] = positions[(pbase + p) * 3u + c];
    }
    if (tid < nP) {
        rec[tid * 32u + 3u] = sizes[pbase + tid];
        rec[tid * 32u + 4u] = densities[pbase + tid];
    }
    __syncthreads();

    const unsigned lane = tid & 31u;
    const unsigned wid  = tid >> 5;
    const unsigned j    = lane & 7u;       // float4 column of the row
    const unsigned rg   = lane >> 3;       // row within 4-row group

    const int   res   = 64 << __ldg(level_p);
    const float fres  = (float)res;
    const int   resm1 = res - 1;

    if (wid < 6u) {
        // ================= STG path: parents 0..23 =================
        #pragma unroll
        for (unsigned w = 0; w < 4u; w++) {
            const unsigned pl = wid * 4u + w;
            if (pl >= nP) break;

            const float* r  = &rec[pl * 32u];
            const float4 v  = *reinterpret_cast<const float4*>(r + 4u * j);
            const float4 ps = *reinterpret_cast<const float4*>(r);

            const float s  = ps.w;
            const float qd = 0.25f * s;    // exact
            const float hs = 0.5f  * s;    // exact

            float* ob = out + (size_t)(pbase + pl) * 256u;

            #pragma unroll
            for (unsigned t = 0; t < 2; t++) {
                const unsigned oct = 4u * t + rg;
                float4 sv = v;
                if (j == 0u) {
                    sv.x = __fadd_rn(ps.x, (oct & 1u) ? qd : -qd);
                    sv.y = __fadd_rn(ps.y, (oct & 2u) ? qd : -qd);
                    sv.z = __fadd_rn(ps.z, (oct & 4u) ? qd : -qd);
                    sv.w = hs;
                }
                __stcs(reinterpret_cast<float4*>(ob + oct * 32u + 4u * j), sv);
            }
        }

        // packed morton for parents 0..23 (threads 0..191, one per child)
        {
            const unsigned pl  = tid >> 3;   // 0..23
            const unsigned oct = tid & 7u;
            if (pl < nP && pl < P_STG) {
                const float4 ps = *reinterpret_cast<const float4*>(&rec[pl * 32u]);
                const float qd = 0.25f * ps.w;
                float px = __fadd_rn(ps.x, (oct & 1u) ? qd : -qd);
                float py = __fadd_rn(ps.y, (oct & 2u) ? qd : -qd);
                float pz = __fadd_rn(ps.z, (oct & 4u) ? qd : -qd);

                unsigned code = (part1by2(coord_of(pz, fres, resm1)) << 2)
                              + (part1by2(coord_of(py, fres, resm1)) << 1)
                              +  part1by2(coord_of(px, fres, resm1));
                __stcs(out + (size_t)nrows * 32u + (size_t)pbase * 8u + tid,
                       (float)(int)code);   // exact: code < 2^21 at level 1
            }
        }
    } else {
        // ================= TMA path: parents 24..31 =================
        const unsigned wt = wid - 6u;        // 0..1

        #pragma unroll
        for (unsigned w = 0; w < 4u; w++) {
            const unsigned plt = wt * 4u + w;        // 0..7 within tile
            const unsigned pl  = P_STG + plt;        // 24..31
            if (pl >= nP) break;

            const float* r  = &rec[pl * 32u];
            const float4 v  = *reinterpret_cast<const float4*>(r + 4u * j);
            const float4 ps = *reinterpret_cast<const float4*>(r);

            const float s  = ps.w;
            const float qd = 0.25f * s;
            const float hs = 0.5f  * s;

            float* tb = &tile[plt * 256u];

            #pragma unroll
            for (unsigned t = 0; t < 2; t++) {
                const unsigned oct = 4u * t + rg;
                float4 sv = v;
                if (j == 0u) {
                    sv.x = __fadd_rn(ps.x, (oct & 1u) ? qd : -qd);
                    sv.y = __fadd_rn(ps.y, (oct & 2u) ? qd : -qd);
                    sv.z = __fadd_rn(ps.z, (oct & 4u) ? qd : -qd);
                    sv.w = hs;
                }
                *reinterpret_cast<float4*>(tb + oct * 32u + 4u * j) = sv;
            }
        }

        // morton for parents 24..31 into smem (64 threads = 64 children)
        {
            const unsigned lt  = tid - 192u;   // 0..63
            const unsigned plt = lt >> 3;      // 0..7
            const unsigned pl  = P_STG + plt;
            const unsigned oct = lt & 7u;
            if (pl < nP) {
                const float4 ps = *reinterpret_cast<const float4*>(&rec[pl * 32u]);
                const float qd = 0.25f * ps.w;
                float px = __fadd_rn(ps.x, (oct & 1u) ? qd : -qd);
                float py = __fadd_rn(ps.y, (oct & 2u) ? qd : -qd);
                float pz = __fadd_rn(ps.z, (oct & 4u) ? qd : -qd);

                unsigned code = (part1by2(coord_of(pz, fres, resm1)) << 2)
                              + (part1by2(coord_of(py, fres, resm1)) << 1)
                              +  part1by2(coord_of(px, fres, resm1));
                mtile[lt] = (float)(int)code;
            }
        }

        // sync the 64 TMA-path threads, then one thread issues the bulk copies
        asm volatile("bar.sync 1, 64;" ::: "memory");

        if (tid == 192u && nP > P_STG) {
            asm volatile("fence.proxy.async.shared::cta;" ::: "memory");

            const unsigned nT = nP - P_STG;                 // parents in tile
            const float* gfeat = out + (size_t)(pbase + P_STG) * 256u;
            const float* gmort = out + (size_t)nrows * 32u
                                     + (size_t)pbase * 8u + P_STG * 8u;
            unsigned feat_bytes = nT * 1024u;               // mult of 16
            unsigned mort_bytes = nT * 32u;                 // mult of 16

            asm volatile(
                "cp.async.bulk.global.shared::cta.bulk_group [%0], [%1], %2;"
                :: "l"(gfeat), "r"(smem_u32(tile)), "r"(feat_bytes) : "memory");
            asm volatile(
                "cp.async.bulk.global.shared::cta.bulk_group [%0], [%1], %2;"
                :: "l"(gmort), "r"(smem_u32(mtile)), "r"(mort_bytes) : "memory");
            asm volatile("cp.async.bulk.commit_group;" ::: "memory");
            // CTA must stay resident until TMA has READ its smem
            asm volatile("cp.async.bulk.wait_group.read 0;" ::: "memory");
        }
    }
}

extern "C" void kernel_launch(void* const* d_in, const int* in_sizes, int n_in,
                              void* d_out, int out_size) {
    const float* positions = (const float*)d_in[0];
    const float* sizes     = (const float*)d_in[1];
    const float* densities = (const float*)d_in[2];
    const float* colors    = (const float*)d_in[3];
    const int*   level     = (const int*)d_in[4];

    unsigned N     = (unsigned)(in_sizes[0] / 3);
    unsigned nrows = N * 8u;

    unsigned blocks = (N + PPB - 1) / PPB;
    asv_expand_kernel<<<blocks, TPB>>>(
        positions, sizes, densities, colors, level,
        (float*)d_out, N, nrows);
}